// round 4
// baseline (speedup 1.0000x reference)
#include <cuda_runtime.h>

#define NSTR   4
#define T_LEN  8192
#define D_HID  2048
#define ND     8192
#define NOUT   24
#define NACC   25
#define KC     128               // k per staged tile
#define NTILES (D_HID / KC)      // 16
#define ROWS_CTA 16              // 4 warps x 4 rows

// partials: [segment][acc][row]
__device__ float g_scratch[NSTR][NACC][T_LEN];   // 3.2 MB

typedef unsigned long long ull;

__device__ __forceinline__ void fma2(ull &acc, ull a, ull b) {
    asm("fma.rn.f32x2 %0, %1, %2, %0;" : "+l"(acc) : "l"(a), "l"(b));
}
__device__ __forceinline__ float lo32(ull v) {
    return __uint_as_float((unsigned)(v & 0xffffffffull));
}
__device__ __forceinline__ float hi32(ull v) {
    return __uint_as_float((unsigned)(v >> 32));
}
__device__ __forceinline__ void cp16(unsigned dst, const float* src) {
    asm volatile("cp.async.cg.shared.global [%0], [%1], 16;\n"
                 :: "r"(dst), "l"(src) : "memory");
}
__device__ __forceinline__ void cp_commit() {
    asm volatile("cp.async.commit_group;\n" ::: "memory");
}
template <int N>
__device__ __forceinline__ void cp_wait() {
    asm volatile("cp.async.wait_group %0;\n" :: "n"(N) : "memory");
}

__global__ __launch_bounds__(128, 4)
void mhc_part(const float* __restrict__ stream,
              const float* __restrict__ Wpre,
              const float* __restrict__ Wpost,
              const float* __restrict__ Wres)
{
    // CTA-shared double-buffered weight tile: [buf][24 rows][128 k]
    __shared__ __align__(16) float ws[2][NOUT][KC];   // 24,576 B

    const int tid  = threadIdx.x;
    const int lane = tid & 31;
    const int w    = tid >> 5;
    const int g    = lane >> 3;          // row within warp's group of 4
    const int c    = lane & 7;           // k-slice (c*4)
    const int rb   = blockIdx.x & 511;   // row block (16 rows)
    const int s    = blockIdx.x >> 9;    // stream segment = k chunk

    const int t = rb * ROWS_CTA + w * 4 + g;

    // x[t][s*2048 + k] = stream[s][t][k]
    const float* xrow = stream + ((size_t)s * T_LEN + t) * D_HID;

    // ---- staging setup: thread stages 6 chunks; chunk i -> weight row j0+4i
    const int j0   = tid >> 5;           // 0..3
    const int off4 = (tid & 31) * 4;     // float offset within 128-float row
    const float* srcs[6];
    srcs[0] = Wpre  + (size_t)j0 * ND + (size_t)s * D_HID + off4;
    srcs[1] = Wpost + (size_t)j0 * ND + (size_t)s * D_HID + off4;
#pragma unroll
    for (int i = 2; i < 6; i++)
        srcs[i] = Wres + (size_t)(j0 + 4 * (i - 2)) * ND + (size_t)s * D_HID + off4;

    const unsigned ws_u32 = (unsigned)__cvta_generic_to_shared(&ws[0][0][0]);
    unsigned dsts[6];
#pragma unroll
    for (int i = 0; i < 6; i++)
        dsts[i] = ws_u32 + (unsigned)(((j0 + 4 * i) * KC + off4) * 4);

    auto stage = [&](int tile, int b) {
        const unsigned boff = (unsigned)(b * NOUT * KC * 4);
#pragma unroll
        for (int i = 0; i < 6; i++)
            cp16(dsts[i] + boff, srcs[i] + tile * KC);
        cp_commit();
    };

    ull acc[NOUT];
#pragma unroll
    for (int i = 0; i < NOUT; i++) acc[i] = 0ull;
    ull accss = 0ull;

    stage(0, 0);

    for (int tile = 0; tile < NTILES; ++tile) {
        const int b = tile & 1;
        if (tile + 1 < NTILES) { stage(tile + 1, b ^ 1); cp_wait<1>(); }
        else                   { cp_wait<0>(); }
        __syncthreads();   // publish tile b

        const ulonglong2* xp =
            reinterpret_cast<const ulonglong2*>(xrow + tile * KC);
        const char* wb = (const char*)&ws[b][0][0];

#pragma unroll
        for (int q = 0; q < 4; ++q) {                 // 4 sub-chunks of 32 k
            const ulonglong2 xv = xp[q * 8 + c];      // lane's 4 x values (nL=4)
            const char* wk = wb + q * 128 + c * 16;
#pragma unroll
            for (int j = 0; j < NOUT; ++j) {
                const ulonglong2 wv =
                    *reinterpret_cast<const ulonglong2*>(wk + j * (KC * 4));
                fma2(acc[j], xv.x, wv.x);
                fma2(acc[j], xv.y, wv.y);
            }
            fma2(accss, xv.x, xv.x);
            fma2(accss, xv.y, xv.y);
        }
        __syncthreads();   // all done with buf b before tile+2 overwrites it
    }

    // merge packed k-halves -> 25 scalars, then reduce over the 8 k-slice lanes
    float resv[NACC];
#pragma unroll
    for (int i = 0; i < NOUT; i++) resv[i] = lo32(acc[i]) + hi32(acc[i]);
    resv[24] = lo32(accss) + hi32(accss);

#pragma unroll
    for (int i = 0; i < NACC; i++) {
        float v = resv[i];
        v += __shfl_down_sync(0xffffffffu, v, 4, 8);
        v += __shfl_down_sync(0xffffffffu, v, 2, 8);
        v += __shfl_down_sync(0xffffffffu, v, 1, 8);
        resv[i] = v;
    }

    if (c == 0) {
#pragma unroll
        for (int i = 0; i < NACC; i++)
            g_scratch[s][i][t] = resv[i];
    }
}

__global__ __launch_bounds__(256)
void mhc_epilogue(const float* __restrict__ bpre,
                  const float* __restrict__ bpost,
                  const float* __restrict__ bres,
                  const float* __restrict__ apre_p,
                  const float* __restrict__ apost_p,
                  const float* __restrict__ ares_p,
                  float* __restrict__ out)
{
    const int t = blockIdx.x * 256 + threadIdx.x;

    float v[NACC];
#pragma unroll
    for (int i = 0; i < NACC; i++)
        v[i] = g_scratch[0][i][t] + g_scratch[1][i][t]
             + g_scratch[2][i][t] + g_scratch[3][i][t];

    const float rn = rsqrtf(v[24] * (1.0f / (float)ND) + 1e-8f);

    const float apre  = *apre_p;
    const float apost = *apost_p;
    const float ares  = *ares_p;

    float* outres  = out;                          // (T,4,4)
    float* outpre  = out + (size_t)T_LEN * 16;     // (T,4)
    float* outpost = out + (size_t)T_LEN * 20;     // (T,4)

#pragma unroll
    for (int k = 0; k < 4; k++) {
        const float z = apre * v[k] * rn + bpre[k];
        outpre[(size_t)t * 4 + k] = 1.0f / (1.0f + expf(-z));
    }
#pragma unroll
    for (int k = 0; k < 4; k++) {
        const float z = apost * v[4 + k] * rn + bpost[k];
        outpost[(size_t)t * 4 + k] = 2.0f / (1.0f + expf(-z));
    }

    float M[16];
#pragma unroll
    for (int i = 0; i < 16; i++)
        M[i] = expf(ares * v[8 + i] * rn + bres[i]);

    for (int it = 0; it < 20; it++) {
#pragma unroll
        for (int a = 0; a < 4; a++) {
            const float r = 1.0f / (M[4*a] + M[4*a+1] + M[4*a+2] + M[4*a+3]);
            M[4*a] *= r; M[4*a+1] *= r; M[4*a+2] *= r; M[4*a+3] *= r;
        }
#pragma unroll
        for (int b = 0; b < 4; b++) {
            const float r = 1.0f / (M[b] + M[4+b] + M[8+b] + M[12+b]);
            M[b] *= r; M[4+b] *= r; M[8+b] *= r; M[12+b] *= r;
        }
    }
#pragma unroll
    for (int i = 0; i < 16; i++) outres[(size_t)t * 16 + i] = M[i];
}

extern "C" void kernel_launch(void* const* d_in, const int* in_sizes, int n_in,
                              void* d_out, int out_size) {
    const float* stream = (const float*)d_in[0];
    const float* Wpre   = (const float*)d_in[1];
    const float* Wpost  = (const float*)d_in[2];
    const float* Wres   = (const float*)d_in[3];
    const float* bpre   = (const float*)d_in[4];
    const float* bpost  = (const float*)d_in[5];
    const float* bres   = (const float*)d_in[6];
    const float* apre   = (const float*)d_in[7];
    const float* apost  = (const float*)d_in[8];
    const float* ares   = (const float*)d_in[9];

    mhc_part<<<512 * NSTR, 128>>>(stream, Wpre, Wpost, Wres);
    mhc_epilogue<<<T_LEN / 256, 256>>>(bpre, bpost, bres, apre, apost, ares,
                                       (float*)d_out);
}

// round 6
// speedup vs baseline: 2.5151x; 2.5151x over previous
#include <cuda_runtime.h>
#include <cuda_bf16.h>
#include <cstdint>

#define NSTR   4
#define T_LEN  8192
#define D_HID  2048
#define ND     8192
#define NOUT   24
#define NACC   25
#define KC     64
#define NT     (D_HID / KC)      // 32 tiles of k per CTA
#define WELEM  1728              // 24 rows * 72 bf16 per packed W tile
#define WBYTES 3456              // 216 * 16

// per-buffer smem layout (bytes)
#define OFF_AHI 0
#define OFF_ALO 16384
#define OFF_BHI 32768
#define OFF_BLO 36352
#define BUF_BYTES 40960
#define SMEM_DYN (1024 + 2 * BUF_BYTES)

// packed bf16 weights: [s*NT + tile][24 rows][72 (64 data + 8 pad)]
__device__ __align__(16) __nv_bfloat16 g_whi[NSTR * NT * WELEM];
__device__ __align__(16) __nv_bfloat16 g_wlo[NSTR * NT * WELEM];
// partials: [segment][acc][row]
__device__ float g_scratch[NSTR][NACC][T_LEN];

__device__ __forceinline__ uint32_t sw128(uint32_t o) {
    return o ^ ((o >> 3) & 0x70u);
}
__device__ __forceinline__ uint32_t cvt2(float lo, float hi) {
    uint32_t r;
    asm("cvt.rn.bf16x2.f32 %0, %1, %2;" : "=r"(r) : "f"(hi), "f"(lo));
    return r;
}
__device__ __forceinline__ void sts64(uint32_t a, uint32_t x, uint32_t y) {
    asm volatile("st.shared.v2.b32 [%0], {%1, %2};" :: "r"(a), "r"(x), "r"(y) : "memory");
}
__device__ __forceinline__ uint32_t lds32(uint32_t a) {
    uint32_t v;
    asm volatile("ld.shared.b32 %0, [%1];" : "=r"(v) : "r"(a));
    return v;
}
__device__ __forceinline__ void cp16(uint32_t dst, const void* src) {
    asm volatile("cp.async.cg.shared.global [%0], [%1], 16;" :: "r"(dst), "l"(src) : "memory");
}
__device__ __forceinline__ void cp_commit() {
    asm volatile("cp.async.commit_group;" ::: "memory");
}
template <int N> __device__ __forceinline__ void cp_wait() {
    asm volatile("cp.async.wait_group %0;" :: "n"(N) : "memory");
}
__device__ __forceinline__ void ldsm4(uint32_t* r, uint32_t addr) {
    asm volatile("ldmatrix.sync.aligned.m8n8.x4.shared.b16 {%0,%1,%2,%3}, [%4];"
                 : "=r"(r[0]), "=r"(r[1]), "=r"(r[2]), "=r"(r[3]) : "r"(addr));
}
__device__ __forceinline__ void mma4(float* d, const uint32_t* a,
                                     uint32_t b0, uint32_t b1) {
    asm volatile(
        "mma.sync.aligned.m16n8k16.row.col.f32.bf16.bf16.f32 "
        "{%0,%1,%2,%3}, {%4,%5,%6,%7}, {%8,%9}, {%0,%1,%2,%3};"
        : "+f"(d[0]), "+f"(d[1]), "+f"(d[2]), "+f"(d[3])
        : "r"(a[0]), "r"(a[1]), "r"(a[2]), "r"(a[3]), "r"(b0), "r"(b1));
}

// ---- W pack: bf16 hi/lo, [24][72] rows per (s,tile) ----
__global__ void mhc_prep(const float* __restrict__ Wpre,
                         const float* __restrict__ Wpost,
                         const float* __restrict__ Wres)
{
    const int id   = blockIdx.x * 256 + threadIdx.x;   // 0..196607
    const int kk   = id & 63;
    const int rest = id >> 6;
    const int j    = rest % 24;
    const int st   = rest / 24;          // s*NT + tile, 0..127
    const int tile = st & 31;
    const int s    = st >> 5;

    const int kg = s * D_HID + tile * KC + kk;
    float v;
    if (j < 4)      v = Wpre [(size_t)j       * ND + kg];
    else if (j < 8) v = Wpost[(size_t)(j - 4) * ND + kg];
    else            v = Wres [(size_t)(j - 8) * ND + kg];

    const __nv_bfloat16 h = __float2bfloat16(v);
    const __nv_bfloat16 l = __float2bfloat16(v - __bfloat162float(h));
    const size_t o = (size_t)st * WELEM + j * 72 + kk;
    g_whi[o] = h;
    g_wlo[o] = l;
}

extern __shared__ unsigned char dsm[];

__global__ __launch_bounds__(256, 2)
void mhc_main_mma(const float* __restrict__ stream)
{
    const int tid  = threadIdx.x;
    const int w    = tid >> 5, lane = tid & 31;
    const int g    = lane >> 3, c = lane & 7;       // X-load mapping
    const int g4   = lane >> 2, t4 = lane & 3;      // mma frag mapping
    const int rb   = blockIdx.x & 63;
    const int s    = blockIdx.x >> 6;
    const int R    = rb * 128;

    const uint32_t raw = (uint32_t)__cvta_generic_to_shared(dsm);
    const uint32_t tb  = (raw + 1023u) & ~1023u;    // 1024-aligned buffers

    const float* xbase = stream + ((size_t)s * T_LEN + R) * D_HID;

    int rr[4];
#pragma unroll
    for (int p = 0; p < 4; p++) rr[p] = p * 32 + w * 4 + g;

    // ldmatrix per-thread A offset (CUTLASS quadrant order)
    const int q    = lane >> 3;
    const int arow = w * 16 + (q & 1) * 8 + (lane & 7);
    const uint32_t aoff = (uint32_t)(arow * 128 + (q >> 1) * 16);

    // B fragment base offset within B tile (row stride 144B)
    const uint32_t boffbase = (uint32_t)(g4 * 144 + t4 * 4);

    float acc[3][4];
#pragma unroll
    for (int j = 0; j < 3; j++)
#pragma unroll
        for (int i = 0; i < 4; i++) acc[j][i] = 0.f;
    float ss[4] = {0.f, 0.f, 0.f, 0.f};

    float4 xr[8];

    auto ldx = [&](int t) {
#pragma unroll
        for (int p = 0; p < 4; p++)
#pragma unroll
            for (int u = 0; u < 2; u++)
                xr[p * 2 + u] = *reinterpret_cast<const float4*>(
                    xbase + (size_t)rr[p] * D_HID + t * KC + (c * 2 + u) * 4);
    };
    auto stage = [&](int t, int b) {
        if (tid < 216) {
            const size_t base = (size_t)(s * NT + t) * WELEM;
            const uint32_t d = tb + (uint32_t)b * BUF_BYTES + tid * 16;
            cp16(d + OFF_BHI, (const unsigned char*)g_whi + base * 2 + tid * 16);
            cp16(d + OFF_BLO, (const unsigned char*)g_wlo + base * 2 + tid * 16);
        }
        cp_commit();
    };
    auto stx = [&](int b) {
        const uint32_t bufb = tb + (uint32_t)b * BUF_BYTES;
#pragma unroll
        for (int p = 0; p < 4; p++) {
#pragma unroll
            for (int u = 0; u < 2; u++) {
                const float4 qv = xr[p * 2 + u];
                const uint32_t h01 = cvt2(qv.x, qv.y);
                const uint32_t h23 = cvt2(qv.z, qv.w);
                const float f0 = __uint_as_float(h01 << 16);
                const float f1 = __uint_as_float(h01 & 0xffff0000u);
                const float f2 = __uint_as_float(h23 << 16);
                const float f3 = __uint_as_float(h23 & 0xffff0000u);
                const uint32_t l01 = cvt2(qv.x - f0, qv.y - f1);
                const uint32_t l23 = cvt2(qv.z - f2, qv.w - f3);
                const uint32_t off = sw128((uint32_t)(rr[p] * 128 + (c * 2 + u) * 8));
                sts64(bufb + OFF_AHI + off, h01, h23);
                sts64(bufb + OFF_ALO + off, l01, l23);
                ss[p] = fmaf(qv.x, qv.x, fmaf(qv.y, qv.y,
                         fmaf(qv.z, qv.z, fmaf(qv.w, qv.w, ss[p]))));
            }
        }
    };

    // preamble: tile 0 into buffer 0
    ldx(0);
    stage(0, 0);
    stx(0);
    cp_wait<0>();
    __syncthreads();

    for (int t = 0; t < NT; ++t) {
        const int b = t & 1;
        const uint32_t bufb = tb + (uint32_t)b * BUF_BYTES;
        const bool pre = (t + 1 < NT);

        if (pre) { ldx(t + 1); stage(t + 1, b ^ 1); }

        // ---- compute tile t ----
#pragma unroll
        for (int kc = 0; kc < 4; kc++) {
            uint32_t ah[4], al[4];
            const uint32_t sa = sw128(aoff + kc * 32);
            ldsm4(ah, bufb + OFF_AHI + sa);
            ldsm4(al, bufb + OFF_ALO + sa);
#pragma unroll
            for (int j = 0; j < 3; j++) {
                const uint32_t bo = boffbase + (uint32_t)(j * 8 * 144 + kc * 32);
                const uint32_t bh0 = lds32(bufb + OFF_BHI + bo);
                const uint32_t bh1 = lds32(bufb + OFF_BHI + bo + 16);
                const uint32_t bl0 = lds32(bufb + OFF_BLO + bo);
                const uint32_t bl1 = lds32(bufb + OFF_BLO + bo + 16);
                mma4(acc[j], ah, bh0, bh1);
                mma4(acc[j], ah, bl0, bl1);
                mma4(acc[j], al, bh0, bh1);
            }
        }

        if (pre) { stx(b ^ 1); cp_wait<0>(); }
        __syncthreads();
    }

    // ---- sumsq: reduce over the 8 k-slice lanes per row ----
#pragma unroll
    for (int p = 0; p < 4; p++) {
        float v = ss[p];
        v += __shfl_down_sync(0xffffffffu, v, 4, 8);
        v += __shfl_down_sync(0xffffffffu, v, 2, 8);
        v += __shfl_down_sync(0xffffffffu, v, 1, 8);
        if (c == 0) g_scratch[s][24][R + rr[p]] = v;
    }

    // ---- write dot partials: warp w owns rows R + w*16 .. +15 ----
    const int row0 = R + w * 16 + g4;
#pragma unroll
    for (int j = 0; j < 3; j++) {
        const int col = j * 8 + t4 * 2;
        g_scratch[s][col    ][row0]     = acc[j][0];
        g_scratch[s][col + 1][row0]     = acc[j][1];
        g_scratch[s][col    ][row0 + 8] = acc[j][2];
        g_scratch[s][col + 1][row0 + 8] = acc[j][3];
    }
}

__global__ __launch_bounds__(64)
void mhc_epilogue(const float* __restrict__ bpre,
                  const float* __restrict__ bpost,
                  const float* __restrict__ bres,
                  const float* __restrict__ apre_p,
                  const float* __restrict__ apost_p,
                  const float* __restrict__ ares_p,
                  float* __restrict__ out)
{
    const int t = blockIdx.x * 64 + threadIdx.x;

    float v[NACC];
#pragma unroll
    for (int i = 0; i < NACC; i++)
        v[i] = g_scratch[0][i][t] + g_scratch[1][i][t]
             + g_scratch[2][i][t] + g_scratch[3][i][t];

    const float rn = rsqrtf(v[24] * (1.0f / (float)ND) + 1e-8f);

    const float apre  = *apre_p;
    const float apost = *apost_p;
    const float ares  = *ares_p;

    float* outres  = out;                          // (T,4,4)
    float* outpre  = out + (size_t)T_LEN * 16;     // (T,4)
    float* outpost = out + (size_t)T_LEN * 20;     // (T,4)

#pragma unroll
    for (int k = 0; k < 4; k++) {
        const float z = apre * v[k] * rn + bpre[k];
        outpre[(size_t)t * 4 + k] = 1.0f / (1.0f + expf(-z));
    }
#pragma unroll
    for (int k = 0; k < 4; k++) {
        const float z = apost * v[4 + k] * rn + bpost[k];
        outpost[(size_t)t * 4 + k] = 2.0f / (1.0f + expf(-z));
    }

    float M[16];
#pragma unroll
    for (int i = 0; i < 16; i++)
        M[i] = expf(ares * v[8 + i] * rn + bres[i]);

    for (int it = 0; it < 20; it++) {
#pragma unroll
        for (int a = 0; a < 4; a++) {
            const float r = 1.0f / (M[4*a] + M[4*a+1] + M[4*a+2] + M[4*a+3]);
            M[4*a] *= r; M[4*a+1] *= r; M[4*a+2] *= r; M[4*a+3] *= r;
        }
#pragma unroll
        for (int b = 0; b < 4; b++) {
            const float r = 1.0f / (M[b] + M[4+b] + M[8+b] + M[12+b]);
            M[b] *= r; M[4+b] *= r; M[8+b] *= r; M[12+b] *= r;
        }
    }
#pragma unroll
    for (int i = 0; i < 16; i++) outres[(size_t)t * 16 + i] = M[i];
}

extern "C" void kernel_launch(void* const* d_in, const int* in_sizes, int n_in,
                              void* d_out, int out_size) {
    const float* stream = (const float*)d_in[0];
    const float* Wpre   = (const float*)d_in[1];
    const float* Wpost  = (const float*)d_in[2];
    const float* Wres   = (const float*)d_in[3];
    const float* bpre   = (const float*)d_in[4];
    const float* bpost  = (const float*)d_in[5];
    const float* bres   = (const float*)d_in[6];
    const float* apre   = (const float*)d_in[7];
    const float* apost  = (const float*)d_in[8];
    const float* ares   = (const float*)d_in[9];

    cudaFuncSetAttribute(mhc_main_mma,
                         cudaFuncAttributeMaxDynamicSharedMemorySize, SMEM_DYN);

    mhc_prep<<<768, 256>>>(Wpre, Wpost, Wres);
    mhc_main_mma<<<256, 256, SMEM_DYN>>>(stream);
    mhc_epilogue<<<T_LEN / 64, 64>>>(bpre, bpost, bres, apre, apost, ares,
                                     (float*)d_out);
}

// round 7
// speedup vs baseline: 2.8768x; 1.1438x over previous
#include <cuda_runtime.h>
#include <cuda_bf16.h>
#include <cstdint>

#define NSTR   4
#define T_LEN  8192
#define D_HID  2048
#define ND     8192
#define NOUT   24
#define NACC   25
#define KC     64
#define NSLOT  8                 // 4 segments x 2 k-halves
#define NT2    16                // tiles per CTA (k = 1024)
#define WELEM  1728              // 24 rows * 72 bf16 per packed W tile

// per-buffer smem layout (bytes)
#define OFF_A  0
#define OFF_B  16384
#define BUF_BYTES 20480
#define SMEM_DYN (1024 + 2 * BUF_BYTES)

// packed bf16 weights: [s*32 + tile][24 rows][72 (64 data + 8 pad)]
__device__ __align__(16) __nv_bfloat16 g_w[NSTR * 32 * WELEM];
// partials: [slot][acc][row]
__device__ float g_scratch[NSLOT][NACC][T_LEN];

__device__ __forceinline__ uint32_t sw128(uint32_t o) {
    return o ^ ((o >> 3) & 0x70u);
}
__device__ __forceinline__ uint32_t cvt2(float lo, float hi) {
    uint32_t r;
    asm("cvt.rn.bf16x2.f32 %0, %1, %2;" : "=r"(r) : "f"(hi), "f"(lo));
    return r;
}
__device__ __forceinline__ void sts64(uint32_t a, uint32_t x, uint32_t y) {
    asm volatile("st.shared.v2.b32 [%0], {%1, %2};" :: "r"(a), "r"(x), "r"(y) : "memory");
}
__device__ __forceinline__ uint32_t lds32(uint32_t a) {
    uint32_t v;
    asm volatile("ld.shared.b32 %0, [%1];" : "=r"(v) : "r"(a));
    return v;
}
__device__ __forceinline__ void cp16(uint32_t dst, const void* src) {
    asm volatile("cp.async.cg.shared.global [%0], [%1], 16;" :: "r"(dst), "l"(src) : "memory");
}
__device__ __forceinline__ void cp_commit() {
    asm volatile("cp.async.commit_group;" ::: "memory");
}
template <int N> __device__ __forceinline__ void cp_wait() {
    asm volatile("cp.async.wait_group %0;" :: "n"(N) : "memory");
}
__device__ __forceinline__ void ldsm4(uint32_t* r, uint32_t addr) {
    asm volatile("ldmatrix.sync.aligned.m8n8.x4.shared.b16 {%0,%1,%2,%3}, [%4];"
                 : "=r"(r[0]), "=r"(r[1]), "=r"(r[2]), "=r"(r[3]) : "r"(addr));
}
__device__ __forceinline__ void mma4(float* d, const uint32_t* a,
                                     uint32_t b0, uint32_t b1) {
    asm volatile(
        "mma.sync.aligned.m16n8k16.row.col.f32.bf16.bf16.f32 "
        "{%0,%1,%2,%3}, {%4,%5,%6,%7}, {%8,%9}, {%0,%1,%2,%3};"
        : "+f"(d[0]), "+f"(d[1]), "+f"(d[2]), "+f"(d[3])
        : "r"(a[0]), "r"(a[1]), "r"(a[2]), "r"(a[3]), "r"(b0), "r"(b1));
}

// ---- W pack: single bf16, [24][72] rows per (s,tile) ----
__global__ void mhc_prep(const float* __restrict__ Wpre,
                         const float* __restrict__ Wpost,
                         const float* __restrict__ Wres)
{
    const int id   = blockIdx.x * 256 + threadIdx.x;   // 0..196607
    const int kk   = id & 63;
    const int rest = id >> 6;
    const int j    = rest % 24;
    const int st   = rest / 24;          // s*32 + tile
    const int tile = st & 31;
    const int s    = st >> 5;

    const int kg = s * D_HID + tile * KC + kk;
    float v;
    if (j < 4)      v = Wpre [(size_t)j       * ND + kg];
    else if (j < 8) v = Wpost[(size_t)(j - 4) * ND + kg];
    else            v = Wres [(size_t)(j - 8) * ND + kg];

    g_w[(size_t)st * WELEM + j * 72 + kk] = __float2bfloat16(v);
}

extern __shared__ unsigned char dsm[];

__global__ __launch_bounds__(256, 3)
void mhc_main_mma(const float* __restrict__ stream)
{
    const int tid  = threadIdx.x;
    const int w    = tid >> 5, lane = tid & 31;
    const int g    = lane >> 3, c = lane & 7;       // X-load mapping
    const int g4   = lane >> 2, t4 = lane & 3;      // mma B-frag mapping
    const int rb   = blockIdx.x & 63;
    const int s2   = blockIdx.x >> 6;               // slot 0..7
    const int s    = s2 >> 1;
    const int half = s2 & 1;
    const int R    = rb * 128;

    const uint32_t raw = (uint32_t)__cvta_generic_to_shared(dsm);
    const uint32_t tb  = (raw + 1023u) & ~1023u;

    const float* xbase = stream + ((size_t)s * T_LEN + R) * D_HID + half * 1024;

    int rr[4];
#pragma unroll
    for (int p = 0; p < 4; p++) rr[p] = p * 32 + w * 4 + g;

    // ldmatrix per-thread A offset (quadrant order)
    const int q    = lane >> 3;
    const int arow = w * 16 + (q & 1) * 8 + (lane & 7);
    const uint32_t aoff = (uint32_t)(arow * 128 + (q >> 1) * 16);

    // B fragment base offset (row stride 144B)
    const uint32_t boffbase = (uint32_t)(g4 * 144 + t4 * 4);

    float acc[3][4];
#pragma unroll
    for (int j = 0; j < 3; j++)
#pragma unroll
        for (int i = 0; i < 4; i++) acc[j][i] = 0.f;
    float ss[4] = {0.f, 0.f, 0.f, 0.f};

    float4 xr[8];

    auto ldx = [&](int t) {
#pragma unroll
        for (int p = 0; p < 4; p++)
#pragma unroll
            for (int u = 0; u < 2; u++)
                xr[p * 2 + u] = *reinterpret_cast<const float4*>(
                    xbase + (size_t)rr[p] * D_HID + t * KC + (c * 2 + u) * 4);
    };
    auto stage = [&](int t, int b) {
        if (tid < 216) {
            const size_t base = (size_t)(s * 32 + half * NT2 + t) * WELEM;
            cp16(tb + (uint32_t)b * BUF_BYTES + OFF_B + tid * 16,
                 (const unsigned char*)g_w + base * 2 + tid * 16);
        }
        cp_commit();
    };
    auto stx = [&](int b) {
        const uint32_t bufb = tb + (uint32_t)b * BUF_BYTES;
#pragma unroll
        for (int p = 0; p < 4; p++) {
#pragma unroll
            for (int u = 0; u < 2; u++) {
                const float4 qv = xr[p * 2 + u];
                const uint32_t h01 = cvt2(qv.x, qv.y);
                const uint32_t h23 = cvt2(qv.z, qv.w);
                const uint32_t off = sw128((uint32_t)(rr[p] * 128 + (c * 2 + u) * 8));
                sts64(bufb + OFF_A + off, h01, h23);
                ss[p] = fmaf(qv.x, qv.x, fmaf(qv.y, qv.y,
                         fmaf(qv.z, qv.z, fmaf(qv.w, qv.w, ss[p]))));
            }
        }
    };

    // preamble: tile 0 into buffer 0
    ldx(0);
    stage(0, 0);
    stx(0);
    cp_wait<0>();
    __syncthreads();

    for (int t = 0; t < NT2; ++t) {
        const int b = t & 1;
        const uint32_t bufb = tb + (uint32_t)b * BUF_BYTES;
        const bool pre = (t + 1 < NT2);

        if (pre) { ldx(t + 1); stage(t + 1, b ^ 1); }

        // ---- compute tile t: 4 k-chunks x 3 n8 tiles, single bf16 product ----
#pragma unroll
        for (int kc = 0; kc < 4; kc++) {
            uint32_t ah[4];
            ldsm4(ah, bufb + OFF_A + sw128(aoff + kc * 32));
#pragma unroll
            for (int j = 0; j < 3; j++) {
                const uint32_t bo = bufb + OFF_B + boffbase
                                  + (uint32_t)(j * 8 * 144 + kc * 32);
                mma4(acc[j], ah, lds32(bo), lds32(bo + 16));
            }
        }

        if (pre) { stx(b ^ 1); cp_wait<0>(); }
        __syncthreads();
    }

    // ---- sumsq: reduce over the 8 k-slice lanes per row ----
#pragma unroll
    for (int p = 0; p < 4; p++) {
        float v = ss[p];
        v += __shfl_down_sync(0xffffffffu, v, 4, 8);
        v += __shfl_down_sync(0xffffffffu, v, 2, 8);
        v += __shfl_down_sync(0xffffffffu, v, 1, 8);
        if (c == 0) g_scratch[s2][24][R + rr[p]] = v;
    }

    // ---- write dot partials: warp w owns rows R + w*16 .. +15 ----
    const int row0 = R + w * 16 + g4;
#pragma unroll
    for (int j = 0; j < 3; j++) {
        const int col = j * 8 + t4 * 2;
        g_scratch[s2][col    ][row0]     = acc[j][0];
        g_scratch[s2][col + 1][row0]     = acc[j][1];
        g_scratch[s2][col    ][row0 + 8] = acc[j][2];
        g_scratch[s2][col + 1][row0 + 8] = acc[j][3];
    }
}

__global__ __launch_bounds__(64)
void mhc_epilogue(const float* __restrict__ bpre,
                  const float* __restrict__ bpost,
                  const float* __restrict__ bres,
                  const float* __restrict__ apre_p,
                  const float* __restrict__ apost_p,
                  const float* __restrict__ ares_p,
                  float* __restrict__ out)
{
    const int t = blockIdx.x * 64 + threadIdx.x;

    float v[NACC];
#pragma unroll
    for (int i = 0; i < NACC; i++) {
        float a = 0.f;
#pragma unroll
        for (int sl = 0; sl < NSLOT; sl++) a += g_scratch[sl][i][t];
        v[i] = a;
    }

    const float rn = rsqrtf(v[24] * (1.0f / (float)ND) + 1e-8f);

    const float apre  = *apre_p;
    const float apost = *apost_p;
    const float ares  = *ares_p;

    float* outres  = out;                          // (T,4,4)
    float* outpre  = out + (size_t)T_LEN * 16;     // (T,4)
    float* outpost = out + (size_t)T_LEN * 20;     // (T,4)

#pragma unroll
    for (int k = 0; k < 4; k++) {
        const float z = apre * v[k] * rn + bpre[k];
        outpre[(size_t)t * 4 + k] = __fdividef(1.0f, 1.0f + __expf(-z));
    }
#pragma unroll
    for (int k = 0; k < 4; k++) {
        const float z = apost * v[4 + k] * rn + bpost[k];
        outpost[(size_t)t * 4 + k] = __fdividef(2.0f, 1.0f + __expf(-z));
    }

    float M[16];
#pragma unroll
    for (int i = 0; i < 16; i++)
        M[i] = __expf(ares * v[8 + i] * rn + bres[i]);

    for (int it = 0; it < 20; it++) {
#pragma unroll
        for (int a = 0; a < 4; a++) {
            const float r = __fdividef(1.0f,
                M[4*a] + M[4*a+1] + M[4*a+2] + M[4*a+3]);
            M[4*a] *= r; M[4*a+1] *= r; M[4*a+2] *= r; M[4*a+3] *= r;
        }
#pragma unroll
        for (int b = 0; b < 4; b++) {
            const float r = __fdividef(1.0f,
                M[b] + M[4+b] + M[8+b] + M[12+b]);
            M[b] *= r; M[4+b] *= r; M[8+b] *= r; M[12+b] *= r;
        }
    }
#pragma unroll
    for (int i = 0; i < 16; i++) outres[(size_t)t * 16 + i] = M[i];
}

extern "C" void kernel_launch(void* const* d_in, const int* in_sizes, int n_in,
                              void* d_out, int out_size) {
    const float* stream = (const float*)d_in[0];
    const float* Wpre   = (const float*)d_in[1];
    const float* Wpost  = (const float*)d_in[2];
    const float* Wres   = (const float*)d_in[3];
    const float* bpre   = (const float*)d_in[4];
    const float* bpost  = (const float*)d_in[5];
    const float* bres   = (const float*)d_in[6];
    const float* apre   = (const float*)d_in[7];
    const float* apost  = (const float*)d_in[8];
    const float* ares   = (const float*)d_in[9];

    cudaFuncSetAttribute(mhc_main_mma,
                         cudaFuncAttributeMaxDynamicSharedMemorySize, SMEM_DYN);

    mhc_prep<<<768, 256>>>(Wpre, Wpost, Wres);
    mhc_main_mma<<<512, 256, SMEM_DYN>>>(stream);
    mhc_epilogue<<<T_LEN / 64, 64>>>(bpre, bpost, bres, apre, apost, ares,
                                     (float*)d_out);
}